// round 12
// baseline (speedup 1.0000x reference)
#include <cuda_runtime.h>
#include <cuda_fp16.h>
#include <cstdint>

#define NN   100000
#define DEG  8
#define HH   128
#define KTOT 1024          // DEG*HH
#define NOUT 384           // 3*HH

// ---------------- device weight images ----------------
__device__ __align__(16) __half g_w1hi[DEG * HH * HH];    // Uf^T  [d][n][k]  fp16 hi
__device__ __align__(16) __half g_w1lo[DEG * HH * HH];    //                  fp16 lo
__device__ __align__(16) __half g_w2hi[NOUT * KTOT];      // Ua^T  [n'][k] interleaved
__device__ __align__(16) __half g_w2lo[NOUT * KTOT];

// ---------------- helpers ----------------
static __device__ __forceinline__ uint32_t smem_u32(const void* p) {
    uint32_t a;
    asm("{ .reg .u64 t; cvta.to.shared.u64 t, %1; cvt.u32.u64 %0, t; }" : "=r"(a) : "l"(p));
    return a;
}
static __device__ __forceinline__ void ldmx4(uint32_t r[4], uint32_t addr) {
    asm volatile("ldmatrix.sync.aligned.m8n8.x4.shared.b16 {%0,%1,%2,%3}, [%4];"
                 : "=r"(r[0]), "=r"(r[1]), "=r"(r[2]), "=r"(r[3]) : "r"(addr));
}
static __device__ __forceinline__ void mma16816(float c[4], const uint32_t a[4], const uint32_t b[2]) {
    asm volatile("mma.sync.aligned.m16n8k16.row.col.f32.f16.f16.f32 "
                 "{%0,%1,%2,%3},{%4,%5,%6,%7},{%8,%9},{%0,%1,%2,%3};"
                 : "+f"(c[0]), "+f"(c[1]), "+f"(c[2]), "+f"(c[3])
                 : "r"(a[0]), "r"(a[1]), "r"(a[2]), "r"(a[3]), "r"(b[0]), "r"(b[1]));
}
static __device__ __forceinline__ void cp16(uint32_t dst, const void* src) {
    asm volatile("cp.async.cg.shared.global [%0], [%1], 16;"
                 :: "r"(dst), "l"(__cvta_generic_to_global(src)) : "memory");
}
#define CP_COMMIT() asm volatile("cp.async.commit_group;" ::: "memory")
#define CP_WAIT0()  asm volatile("cp.async.wait_group 0;" ::: "memory")

static __device__ __forceinline__ float sigm(float x) { return 1.f / (1.f + __expf(-x)); }
static __device__ __forceinline__ uint32_t pack2h(float a, float b) {
    __half2 h = __floats2half2_rn(a, b);
    return *reinterpret_cast<uint32_t*>(&h);
}

// ---------------- prep: transpose + fp16 hi/lo split of weights ----------------
__global__ void prep_weights(const float* __restrict__ Uf, const float* __restrict__ Ua) {
    int t = blockIdx.x * blockDim.x + threadIdx.x;
    if (t < DEG * HH * HH) {                 // W1: [d][n][k] = Uf[d][k][n]
        int k = t & 127, n = (t >> 7) & 127, d = t >> 14;
        float v = Uf[((size_t)d * HH + k) * HH + n];
        __half hb = __float2half_rn(v);
        g_w1hi[t] = hb;
        g_w1lo[t] = __float2half_rn(v - __half2float(hb));
        return;
    }
    int u = t - DEG * HH * HH;
    if (u < NOUT * KTOT) {                   // W2: n' = grp*24 + ch*8 + c8
        int k = u & 1023, np = u >> 10;
        int grp = np / 24, rem = np - grp * 24;
        int ch = rem >> 3, c8 = rem & 7;
        int col = grp * 8 + c8;
        int d = k >> 7, h = k & 127;
        float v = Ua[((size_t)d * HH + h) * NOUT + ch * HH + col];
        __half hb = __float2half_rn(v);
        g_w2hi[u] = hb;
        g_w2lo[u] = __float2half_rn(v - __half2float(hb));
    }
}

// =====================================================================
// Fused kernel: 256 thr (8 warps 2m x 4n), M=64.
// Per half-CTA (blockIdx.y): iou N=192 (interleaved half) + f N=64
// (W1 cols [nhalf*64, nhalf*64+64)).  c_aggr stays in registers;
// fragment cols of f and iou line up (fn == g), so no scratch.
// =====================================================================
#define BST   80
#define S_BIH 0          // B iou hi : 192*80 = 15360
#define S_BIL 15360
#define S_BFH 30720      // B f hi   :  64*80 =  5120
#define S_BFL 35840
#define S_SA  40960      // A        :  64*80 =  5120
#define STAGE 46080
#define SMEM_TOTAL (2 * STAGE)   // 92160

__global__ __launch_bounds__(256, 2)
void fused_cell(const float* __restrict__ nh, const float* __restrict__ ncv,
                const float* __restrict__ f_in, const float* __restrict__ iou_in,
                const float* __restrict__ bf, const float* __restrict__ ba,
                float* __restrict__ out) {
    extern __shared__ unsigned char smb[];
    const uint32_t sb = smem_u32(smb);
    const int tid = threadIdx.x, wid = tid >> 5, l = tid & 31;
    const int wm = wid & 1, wn = wid >> 1;
    const int nb = blockIdx.x * 64;
    const int nhalf = blockIdx.y;               // 0 or 1
    const int brow0 = nhalf * 192;              // iou B rows
    const int fcol0 = nhalf * 64;               // f (W1) column base

    uint32_t aoff[2], boff[3], bfoff;
#pragma unroll
    for (int fm = 0; fm < 2; fm++)
        aoff[fm] = (uint32_t)(wm * 32 + fm * 16 + (l & 15)) * BST + (uint32_t)(l >> 4) * 16;
#pragma unroll
    for (int p = 0; p < 3; p++)
        boff[p] = (uint32_t)(wn * 48 + p * 16 + (l & 7) + ((l >> 4) ? 8 : 0)) * BST
                + (uint32_t)((l >> 3) & 1) * 16;
    bfoff = (uint32_t)(wn * 16 + (l & 7) + ((l >> 4) ? 8 : 0)) * BST
          + (uint32_t)((l >> 3) & 1) * 16;

    float acc[2][6][4];                  // iou
    float accf[2][2][4], cag[2][2][4];   // f + c_aggr (16 cols per warp)
#pragma unroll
    for (int a = 0; a < 2; a++) {
#pragma unroll
        for (int b = 0; b < 6; b++)
#pragma unroll
            for (int c = 0; c < 4; c++) acc[a][b][c] = 0.f;
#pragma unroll
        for (int b = 0; b < 2; b++)
#pragma unroll
            for (int c = 0; c < 4; c++) { accf[a][b][c] = 0.f; cag[a][b][c] = 0.f; }
    }

    const int arow = tid >> 2, aq = tid & 3;
    const int anode = nb + arow;
    const float* asrc = nh + (size_t)anode * KTOT + aq * 8;

    // ---- prologue: chunk 0 ----
    {
#pragma unroll
        for (int i = 0; i < 3; i++) {           // B iou: 768 granule-pairs
            int idx = tid + i * 256;
            int r = idx >> 2, g = idx & 3;
            uint32_t doff = sb + r * BST + g * 16;
            cp16(doff + S_BIH, (const char*)(g_w2hi + (size_t)(brow0 + r) * KTOT) + g * 16);
            cp16(doff + S_BIL, (const char*)(g_w2lo + (size_t)(brow0 + r) * KTOT) + g * 16);
        }
        {                                        // B f: 256 granule-pairs
            int r = tid >> 2, g = tid & 3;
            uint32_t doff = sb + r * BST + g * 16;
            cp16(doff + S_BFH, (const char*)(g_w1hi + (size_t)(fcol0 + r) * HH) + g * 16);
            cp16(doff + S_BFL, (const char*)(g_w1lo + (size_t)(fcol0 + r) * HH) + g * 16);
        }
        CP_COMMIT();
        float4 v0 = make_float4(0,0,0,0), v1 = v0;
        if (anode < NN) { v0 = *(const float4*)(asrc); v1 = *(const float4*)(asrc + 4); }
        uint32_t h0 = pack2h(v0.x, v0.y), h1 = pack2h(v0.z, v0.w);
        uint32_t h2 = pack2h(v1.x, v1.y), h3 = pack2h(v1.z, v1.w);
        uint32_t ad = sb + S_SA + arow * BST + aq * 16;
        asm volatile("st.shared.v4.b32 [%0], {%1,%2,%3,%4};" :: "r"(ad), "r"(h0), "r"(h1), "r"(h2), "r"(h3) : "memory");
        CP_WAIT0();
        __syncthreads();
    }

    for (int kc = 0; kc < 32; kc++) {
        const uint32_t cur = sb + (kc & 1) * STAGE;
        const uint32_t nxt = sb + ((kc + 1) & 1) * STAGE;
        const bool have_next = (kc < 31);

        float4 v0, v1;
        if (have_next) {
            v0 = make_float4(0,0,0,0); v1 = v0;
            if (anode < NN) {
                v0 = *(const float4*)(asrc + (kc + 1) * 32);
                v1 = *(const float4*)(asrc + (kc + 1) * 32 + 4);
            }
            int dn = (kc + 1) >> 2, sl = (kc + 1) & 3;
#pragma unroll
            for (int i = 0; i < 3; i++) {
                int idx = tid + i * 256;
                int r = idx >> 2, g = idx & 3;
                uint32_t doff = nxt + r * BST + g * 16;
                cp16(doff + S_BIH, (const char*)(g_w2hi + (size_t)(brow0 + r) * KTOT) + (kc + 1) * 64 + g * 16);
                cp16(doff + S_BIL, (const char*)(g_w2lo + (size_t)(brow0 + r) * KTOT) + (kc + 1) * 64 + g * 16);
            }
            {
                int r = tid >> 2, g = tid & 3;
                uint32_t doff = nxt + r * BST + g * 16;
                cp16(doff + S_BFH, (const char*)(g_w1hi + ((size_t)dn * HH + fcol0 + r) * HH) + sl * 64 + g * 16);
                cp16(doff + S_BFL, (const char*)(g_w1lo + ((size_t)dn * HH + fcol0 + r) * HH) + sl * 64 + g * 16);
            }
            CP_COMMIT();
        }

        // ---- compute (2-term: A*Bhi + A*Blo) ----
#pragma unroll
        for (int ks = 0; ks < 2; ks++) {
            uint32_t ah[2][4];
#pragma unroll
            for (int fm = 0; fm < 2; fm++)
                ldmx4(ah[fm], cur + S_SA + aoff[fm] + ks * 32);
#pragma unroll
            for (int p = 0; p < 3; p++) {
                uint32_t rh4[4], rl4[4];
                ldmx4(rh4, cur + S_BIH + boff[p] + ks * 32);
                ldmx4(rl4, cur + S_BIL + boff[p] + ks * 32);
                mma16816(acc[0][p*2+0], ah[0], rh4 + 0);
                mma16816(acc[0][p*2+1], ah[0], rh4 + 2);
                mma16816(acc[1][p*2+0], ah[1], rh4 + 0);
                mma16816(acc[1][p*2+1], ah[1], rh4 + 2);
                mma16816(acc[0][p*2+0], ah[0], rl4 + 0);
                mma16816(acc[0][p*2+1], ah[0], rl4 + 2);
                mma16816(acc[1][p*2+0], ah[1], rl4 + 0);
                mma16816(acc[1][p*2+1], ah[1], rl4 + 2);
            }
            {   // f gate (current d, this CTA's 64-col half)
                uint32_t rh4[4], rl4[4];
                ldmx4(rh4, cur + S_BFH + bfoff + ks * 32);
                ldmx4(rl4, cur + S_BFL + bfoff + ks * 32);
                mma16816(accf[0][0], ah[0], rh4 + 0);
                mma16816(accf[0][1], ah[0], rh4 + 2);
                mma16816(accf[1][0], ah[1], rh4 + 0);
                mma16816(accf[1][1], ah[1], rh4 + 2);
                mma16816(accf[0][0], ah[0], rl4 + 0);
                mma16816(accf[0][1], ah[0], rl4 + 2);
                mma16816(accf[1][0], ah[1], rl4 + 0);
                mma16816(accf[1][1], ah[1], rl4 + 2);
            }
        }

        // ---- f epilogue at end of each d ----
        if ((kc & 3) == 3) {
            const int d = kc >> 2;
#pragma unroll
            for (int fm = 0; fm < 2; fm++)
#pragma unroll
                for (int rh = 0; rh < 2; rh++) {
                    int node = nb + wm * 32 + fm * 16 + (l >> 2) + rh * 8;
                    if (node < NN) {
#pragma unroll
                        for (int fn = 0; fn < 2; fn++) {
                            int col = fcol0 + wn * 16 + fn * 8 + (l & 3) * 2;
                            float2 fi  = *(const float2*)(f_in + (size_t)node * HH + col);
                            float2 nc2 = *(const float2*)(ncv + ((size_t)node * DEG + d) * HH + col);
                            float2 bf2 = *(const float2*)(bf + d * HH + col);
                            cag[fm][fn][rh*2+0] += sigm(accf[fm][fn][rh*2+0] + bf2.x + fi.x) * nc2.x;
                            cag[fm][fn][rh*2+1] += sigm(accf[fm][fn][rh*2+1] + bf2.y + fi.y) * nc2.y;
                        }
                    }
#pragma unroll
                    for (int fn = 0; fn < 2; fn++) {
                        accf[fm][fn][rh*2+0] = 0.f;
                        accf[fm][fn][rh*2+1] = 0.f;
                    }
                }
        }

        if (have_next) {
            uint32_t h0 = pack2h(v0.x, v0.y), h1 = pack2h(v0.z, v0.w);
            uint32_t h2 = pack2h(v1.x, v1.y), h3 = pack2h(v1.z, v1.w);
            uint32_t ad = nxt + S_SA + arow * BST + aq * 16;
            asm volatile("st.shared.v4.b32 [%0], {%1,%2,%3,%4};" :: "r"(ad), "r"(h0), "r"(h1), "r"(h2), "r"(h3) : "memory");
            CP_WAIT0();
            __syncthreads();
        }
    }

    // ---- final epilogue: cols [nhalf*64, nhalf*64+64), cag in regs ----
#pragma unroll
    for (int fm = 0; fm < 2; fm++)
#pragma unroll
        for (int rh = 0; rh < 2; rh++) {
            int node = nb + wm * 32 + fm * 16 + (l >> 2) + rh * 8;
            if (node >= NN) continue;
            const float* ib = iou_in + (size_t)node * NOUT;
#pragma unroll
            for (int g = 0; g < 2; g++) {
                int col = (nhalf * 8 + wn * 2 + g) * 8 + (l & 3) * 2;  // == fcol0 + wn*16 + g*8 + (l&3)*2
                float2 ii = *(const float2*)(ib + col);
                float2 oo = *(const float2*)(ib + HH + col);
                float2 uu = *(const float2*)(ib + 2 * HH + col);
                float2 bi = *(const float2*)(ba + col);
                float2 bo = *(const float2*)(ba + HH + col);
                float2 bu = *(const float2*)(ba + 2 * HH + col);
                float hv[2], cv[2];
#pragma unroll
                for (int e = 0; e < 2; e++) {
                    float iv = acc[fm][g*3+0][rh*2+e] + ((e) ? ii.y + bi.y : ii.x + bi.x);
                    float ov = acc[fm][g*3+1][rh*2+e] + ((e) ? oo.y + bo.y : oo.x + bo.x);
                    float uv = acc[fm][g*3+2][rh*2+e] + ((e) ? uu.y + bu.y : uu.x + bu.x);
                    float c  = sigm(iv) * tanhf(uv) + cag[fm][g][rh*2+e];
                    cv[e] = c;
                    hv[e] = sigm(ov) * tanhf(c);
                }
                *(float2*)(out + (size_t)node * HH + col) = make_float2(hv[0], hv[1]);
                *(float2*)(out + (size_t)NN * HH + (size_t)node * HH + col) = make_float2(cv[0], cv[1]);
            }
        }
}

// ---------------- launch ----------------
extern "C" void kernel_launch(void* const* d_in, const int* in_sizes, int n_in,
                              void* d_out, int out_size) {
    const float* nh     = (const float*)d_in[0];
    const float* ncv    = (const float*)d_in[1];
    const float* f_in   = (const float*)d_in[2];
    const float* iou_in = (const float*)d_in[3];
    const float* Uf     = (const float*)d_in[4];
    const float* bf     = (const float*)d_in[5];
    const float* Ua     = (const float*)d_in[6];
    const float* ba     = (const float*)d_in[7];
    float* out = (float*)d_out;

    prep_weights<<<2048, 256>>>(Uf, Ua);

    cudaFuncSetAttribute(fused_cell, cudaFuncAttributeMaxDynamicSharedMemorySize, SMEM_TOTAL);
    dim3 grid((NN + 63) / 64, 2);
    fused_cell<<<grid, 256, SMEM_TOTAL>>>(nh, ncv, f_in, iou_in, bf, ba, out);
}

// round 13
// speedup vs baseline: 1.2824x; 1.2824x over previous
#include <cuda_runtime.h>
#include <cuda_fp16.h>
#include <cstdint>

#define NN   100000
#define DEG  8
#define HH   128
#define KTOT 1024          // DEG*HH
#define NOUT 384           // 3*HH

// ---------------- device weight images (single fp16) ----------------
__device__ __align__(16) __half g_w1[DEG * HH * HH];      // Uf^T  [d][n][k]
__device__ __align__(16) __half g_w2[NOUT * KTOT];        // Ua^T  [n'][k] interleaved

// ---------------- helpers ----------------
static __device__ __forceinline__ uint32_t smem_u32(const void* p) {
    uint32_t a;
    asm("{ .reg .u64 t; cvta.to.shared.u64 t, %1; cvt.u32.u64 %0, t; }" : "=r"(a) : "l"(p));
    return a;
}
static __device__ __forceinline__ void ldmx4(uint32_t r[4], uint32_t addr) {
    asm volatile("ldmatrix.sync.aligned.m8n8.x4.shared.b16 {%0,%1,%2,%3}, [%4];"
                 : "=r"(r[0]), "=r"(r[1]), "=r"(r[2]), "=r"(r[3]) : "r"(addr));
}
static __device__ __forceinline__ void mma16816(float c[4], const uint32_t a[4], const uint32_t b[2]) {
    asm volatile("mma.sync.aligned.m16n8k16.row.col.f32.f16.f16.f32 "
                 "{%0,%1,%2,%3},{%4,%5,%6,%7},{%8,%9},{%0,%1,%2,%3};"
                 : "+f"(c[0]), "+f"(c[1]), "+f"(c[2]), "+f"(c[3])
                 : "r"(a[0]), "r"(a[1]), "r"(a[2]), "r"(a[3]), "r"(b[0]), "r"(b[1]));
}
static __device__ __forceinline__ void cp16(uint32_t dst, const void* src) {
    asm volatile("cp.async.cg.shared.global [%0], [%1], 16;"
                 :: "r"(dst), "l"(__cvta_generic_to_global(src)) : "memory");
}
#define CP_COMMIT() asm volatile("cp.async.commit_group;" ::: "memory")
#define CP_WAIT0()  asm volatile("cp.async.wait_group 0;" ::: "memory")

static __device__ __forceinline__ float sigm(float x) { return 1.f / (1.f + __expf(-x)); }
static __device__ __forceinline__ uint32_t pack2h(float a, float b) {
    __half2 h = __floats2half2_rn(a, b);
    return *reinterpret_cast<uint32_t*>(&h);
}

// ---------------- prep: transpose weights to fp16 ----------------
__global__ void prep_weights(const float* __restrict__ Uf, const float* __restrict__ Ua) {
    int t = blockIdx.x * blockDim.x + threadIdx.x;
    if (t < DEG * HH * HH) {                 // W1: [d][n][k] = Uf[d][k][n]
        int k = t & 127, n = (t >> 7) & 127, d = t >> 14;
        g_w1[t] = __float2half_rn(Uf[((size_t)d * HH + k) * HH + n]);
        return;
    }
    int u = t - DEG * HH * HH;
    if (u < NOUT * KTOT) {                   // W2: n' = grp*24 + ch*8 + c8
        int k = u & 1023, np = u >> 10;
        int grp = np / 24, rem = np - grp * 24;
        int ch = rem >> 3, c8 = rem & 7;
        int col = grp * 8 + c8;
        int d = k >> 7, h = k & 127;
        g_w2[u] = __float2half_rn(Ua[((size_t)d * HH + h) * NOUT + ch * HH + col]);
    }
}

// =====================================================================
// Fused kernel: 256 thr (8 warps 2m x 4n), M=64.
// Per half-CTA (blockIdx.y): iou N=192 (interleaved half) + f N=64
// (W1 cols [nhalf*64, nhalf*64+64)).  Single fp16 term per product.
// =====================================================================
#define BST   80
#define S_BI  0          // B iou : 192*80 = 15360
#define S_BF  15360      // B f   :  64*80 =  5120
#define S_SA  20480      // A     :  64*80 =  5120
#define STAGE 25600
#define SMEM_TOTAL (2 * STAGE)   // 51200

__global__ __launch_bounds__(256, 2)
void fused_cell(const float* __restrict__ nh, const float* __restrict__ ncv,
                const float* __restrict__ f_in, const float* __restrict__ iou_in,
                const float* __restrict__ bf, const float* __restrict__ ba,
                float* __restrict__ out) {
    extern __shared__ unsigned char smb[];
    const uint32_t sb = smem_u32(smb);
    const int tid = threadIdx.x, wid = tid >> 5, l = tid & 31;
    const int wm = wid & 1, wn = wid >> 1;
    const int nb = blockIdx.x * 64;
    const int nhalf = blockIdx.y;               // 0 or 1
    const int brow0 = nhalf * 192;              // iou B rows
    const int fcol0 = nhalf * 64;               // f (W1) column base

    uint32_t aoff[2], boff[3], bfoff;
#pragma unroll
    for (int fm = 0; fm < 2; fm++)
        aoff[fm] = (uint32_t)(wm * 32 + fm * 16 + (l & 15)) * BST + (uint32_t)(l >> 4) * 16;
#pragma unroll
    for (int p = 0; p < 3; p++)
        boff[p] = (uint32_t)(wn * 48 + p * 16 + (l & 7) + ((l >> 4) ? 8 : 0)) * BST
                + (uint32_t)((l >> 3) & 1) * 16;
    bfoff = (uint32_t)(wn * 16 + (l & 7) + ((l >> 4) ? 8 : 0)) * BST
          + (uint32_t)((l >> 3) & 1) * 16;

    float acc[2][6][4];                  // iou
    float accf[2][2][4], cag[2][2][4];   // f + c_aggr (16 cols per warp)
#pragma unroll
    for (int a = 0; a < 2; a++) {
#pragma unroll
        for (int b = 0; b < 6; b++)
#pragma unroll
            for (int c = 0; c < 4; c++) acc[a][b][c] = 0.f;
#pragma unroll
        for (int b = 0; b < 2; b++)
#pragma unroll
            for (int c = 0; c < 4; c++) { accf[a][b][c] = 0.f; cag[a][b][c] = 0.f; }
    }

    const int arow = tid >> 2, aq = tid & 3;
    const int anode = nb + arow;
    const float* asrc = nh + (size_t)anode * KTOT + aq * 8;

    // ---- prologue: chunk 0 ----
    {
#pragma unroll
        for (int i = 0; i < 3; i++) {           // B iou: 768 granules
            int idx = tid + i * 256;
            int r = idx >> 2, g = idx & 3;
            cp16(sb + S_BI + r * BST + g * 16,
                 (const char*)(g_w2 + (size_t)(brow0 + r) * KTOT) + g * 16);
        }
        {                                        // B f: 256 granules
            int r = tid >> 2, g = tid & 3;
            cp16(sb + S_BF + r * BST + g * 16,
                 (const char*)(g_w1 + (size_t)(fcol0 + r) * HH) + g * 16);
        }
        CP_COMMIT();
        float4 v0 = make_float4(0,0,0,0), v1 = v0;
        if (anode < NN) { v0 = *(const float4*)(asrc); v1 = *(const float4*)(asrc + 4); }
        uint32_t h0 = pack2h(v0.x, v0.y), h1 = pack2h(v0.z, v0.w);
        uint32_t h2 = pack2h(v1.x, v1.y), h3 = pack2h(v1.z, v1.w);
        uint32_t ad = sb + S_SA + arow * BST + aq * 16;
        asm volatile("st.shared.v4.b32 [%0], {%1,%2,%3,%4};" :: "r"(ad), "r"(h0), "r"(h1), "r"(h2), "r"(h3) : "memory");
        CP_WAIT0();
        __syncthreads();
    }

    for (int kc = 0; kc < 32; kc++) {
        const uint32_t cur = sb + (kc & 1) * STAGE;
        const uint32_t nxt = sb + ((kc + 1) & 1) * STAGE;
        const bool have_next = (kc < 31);

        float4 v0, v1;
        if (have_next) {
            v0 = make_float4(0,0,0,0); v1 = v0;
            if (anode < NN) {
                v0 = *(const float4*)(asrc + (kc + 1) * 32);
                v1 = *(const float4*)(asrc + (kc + 1) * 32 + 4);
            }
            int dn = (kc + 1) >> 2, sl = (kc + 1) & 3;
#pragma unroll
            for (int i = 0; i < 3; i++) {
                int idx = tid + i * 256;
                int r = idx >> 2, g = idx & 3;
                cp16(nxt + S_BI + r * BST + g * 16,
                     (const char*)(g_w2 + (size_t)(brow0 + r) * KTOT) + (kc + 1) * 64 + g * 16);
            }
            {
                int r = tid >> 2, g = tid & 3;
                cp16(nxt + S_BF + r * BST + g * 16,
                     (const char*)(g_w1 + ((size_t)dn * HH + fcol0 + r) * HH) + sl * 64 + g * 16);
            }
            CP_COMMIT();
        }

        // ---- compute (single fp16 term) ----
#pragma unroll
        for (int ks = 0; ks < 2; ks++) {
            uint32_t ah[2][4];
#pragma unroll
            for (int fm = 0; fm < 2; fm++)
                ldmx4(ah[fm], cur + S_SA + aoff[fm] + ks * 32);
#pragma unroll
            for (int p = 0; p < 3; p++) {
                uint32_t rh4[4];
                ldmx4(rh4, cur + S_BI + boff[p] + ks * 32);
                mma16816(acc[0][p*2+0], ah[0], rh4 + 0);
                mma16816(acc[0][p*2+1], ah[0], rh4 + 2);
                mma16816(acc[1][p*2+0], ah[1], rh4 + 0);
                mma16816(acc[1][p*2+1], ah[1], rh4 + 2);
            }
            {   // f gate (current d, this CTA's 64-col half)
                uint32_t rh4[4];
                ldmx4(rh4, cur + S_BF + bfoff + ks * 32);
                mma16816(accf[0][0], ah[0], rh4 + 0);
                mma16816(accf[0][1], ah[0], rh4 + 2);
                mma16816(accf[1][0], ah[1], rh4 + 0);
                mma16816(accf[1][1], ah[1], rh4 + 2);
            }
        }

        // ---- f epilogue at end of each d ----
        if ((kc & 3) == 3) {
            const int d = kc >> 2;
#pragma unroll
            for (int fm = 0; fm < 2; fm++)
#pragma unroll
                for (int rh = 0; rh < 2; rh++) {
                    int node = nb + wm * 32 + fm * 16 + (l >> 2) + rh * 8;
                    if (node < NN) {
#pragma unroll
                        for (int fn = 0; fn < 2; fn++) {
                            int col = fcol0 + wn * 16 + fn * 8 + (l & 3) * 2;
                            float2 fi  = *(const float2*)(f_in + (size_t)node * HH + col);
                            float2 nc2 = *(const float2*)(ncv + ((size_t)node * DEG + d) * HH + col);
                            float2 bf2 = *(const float2*)(bf + d * HH + col);
                            cag[fm][fn][rh*2+0] += sigm(accf[fm][fn][rh*2+0] + bf2.x + fi.x) * nc2.x;
                            cag[fm][fn][rh*2+1] += sigm(accf[fm][fn][rh*2+1] + bf2.y + fi.y) * nc2.y;
                        }
                    }
#pragma unroll
                    for (int fn = 0; fn < 2; fn++) {
                        accf[fm][fn][rh*2+0] = 0.f;
                        accf[fm][fn][rh*2+1] = 0.f;
                    }
                }
        }

        if (have_next) {
            uint32_t h0 = pack2h(v0.x, v0.y), h1 = pack2h(v0.z, v0.w);
            uint32_t h2 = pack2h(v1.x, v1.y), h3 = pack2h(v1.z, v1.w);
            uint32_t ad = nxt + S_SA + arow * BST + aq * 16;
            asm volatile("st.shared.v4.b32 [%0], {%1,%2,%3,%4};" :: "r"(ad), "r"(h0), "r"(h1), "r"(h2), "r"(h3) : "memory");
            CP_WAIT0();
            __syncthreads();
        }
    }

    // ---- final epilogue: cols [nhalf*64, nhalf*64+64), cag in regs ----
#pragma unroll
    for (int fm = 0; fm < 2; fm++)
#pragma unroll
        for (int rh = 0; rh < 2; rh++) {
            int node = nb + wm * 32 + fm * 16 + (l >> 2) + rh * 8;
            if (node >= NN) continue;
            const float* ib = iou_in + (size_t)node * NOUT;
#pragma unroll
            for (int g = 0; g < 2; g++) {
                int col = (nhalf * 8 + wn * 2 + g) * 8 + (l & 3) * 2;  // == fcol0 + wn*16 + g*8 + (l&3)*2
                float2 ii = *(const float2*)(ib + col);
                float2 oo = *(const float2*)(ib + HH + col);
                float2 uu = *(const float2*)(ib + 2 * HH + col);
                float2 bi = *(const float2*)(ba + col);
                float2 bo = *(const float2*)(ba + HH + col);
                float2 bu = *(const float2*)(ba + 2 * HH + col);
                float hv[2], cv[2];
#pragma unroll
                for (int e = 0; e < 2; e++) {
                    float iv = acc[fm][g*3+0][rh*2+e] + ((e) ? ii.y + bi.y : ii.x + bi.x);
                    float ov = acc[fm][g*3+1][rh*2+e] + ((e) ? oo.y + bo.y : oo.x + bo.x);
                    float uv = acc[fm][g*3+2][rh*2+e] + ((e) ? uu.y + bu.y : uu.x + bu.x);
                    float c  = sigm(iv) * tanhf(uv) + cag[fm][g][rh*2+e];
                    cv[e] = c;
                    hv[e] = sigm(ov) * tanhf(c);
                }
                *(float2*)(out + (size_t)node * HH + col) = make_float2(hv[0], hv[1]);
                *(float2*)(out + (size_t)NN * HH + (size_t)node * HH + col) = make_float2(cv[0], cv[1]);
            }
        }
}

// ---------------- launch ----------------
extern "C" void kernel_launch(void* const* d_in, const int* in_sizes, int n_in,
                              void* d_out, int out_size) {
    const float* nh     = (const float*)d_in[0];
    const float* ncv    = (const float*)d_in[1];
    const float* f_in   = (const float*)d_in[2];
    const float* iou_in = (const float*)d_in[3];
    const float* Uf     = (const float*)d_in[4];
    const float* bf     = (const float*)d_in[5];
    const float* Ua     = (const float*)d_in[6];
    const float* ba     = (const float*)d_in[7];
    float* out = (float*)d_out;

    prep_weights<<<2048, 256>>>(Uf, Ua);

    cudaFuncSetAttribute(fused_cell, cudaFuncAttributeMaxDynamicSharedMemorySize, SMEM_TOTAL);
    dim3 grid((NN + 63) / 64, 2);
    fused_cell<<<grid, 256, SMEM_TOTAL>>>(nh, ncv, f_in, iou_in, bf, ba, out);
}